// round 11
// baseline (speedup 1.0000x reference)
#include <cuda_runtime.h>
#include <cuda_bf16.h>
#include <cstdint>
#include <math.h>

// Problem dims (fixed)
#define BB    8
#define HH    64
#define WWID  64
#define CC    512
#define CFG   64
#define CHDIM 256
#define HW    4096
#define HWD   1024
#define MROWS 32768          // BB*HW
#define NPROJ 384            // CFG + CFG + CHDIM

typedef __nv_bfloat16 bf16;
typedef __nv_bfloat162 bf162;

// -------------------- device scratch (BSS, allocation-free) ----------------
__device__ bf16  d_wcat [(size_t)CC * NPROJ];         // [theta|phi|g] weights
__device__ bf16  d_owbf [(size_t)CHDIM * CC];         // o3 weights
__device__ float d_bcat [NPROJ];                      // [theta|phi|g] biases
__device__ bf16  d_projbf[(size_t)MROWS * NPROJ];     // projections pre-pool
__device__ bf16  d_phibf[(size_t)BB * HWD * CFG];
__device__ bf16  d_gbf  [(size_t)BB * HWD * CHDIM];   // pooled g, scaled by 1/Z
__device__ bf16  d_ebf  [(size_t)BB * HWD * HW];      // e = exp(s), unnormalized
__device__ float d_part [(size_t)BB * HWD * 4];       // per-(row, jgroup) partials
__device__ bf16  d_obf  [(size_t)MROWS * CHDIM];      // attention out

// -------------------- PTX helpers -----------------------------------------
__device__ __forceinline__ unsigned smem_u32(const void* p) {
    return (unsigned)__cvta_generic_to_shared(p);
}
__device__ __forceinline__ void ldsm_x4(unsigned a[4], unsigned addr) {
    asm volatile("ldmatrix.sync.aligned.m8n8.x4.shared.b16 {%0,%1,%2,%3}, [%4];"
        : "=r"(a[0]), "=r"(a[1]), "=r"(a[2]), "=r"(a[3]) : "r"(addr));
}
__device__ __forceinline__ void ldsm_x4_t(unsigned a[4], unsigned addr) {
    asm volatile("ldmatrix.sync.aligned.m8n8.x4.trans.shared.b16 {%0,%1,%2,%3}, [%4];"
        : "=r"(a[0]), "=r"(a[1]), "=r"(a[2]), "=r"(a[3]) : "r"(addr));
}
__device__ __forceinline__ void ldsm_x2(unsigned b[2], unsigned addr) {
    asm volatile("ldmatrix.sync.aligned.m8n8.x2.shared.b16 {%0,%1}, [%2];"
        : "=r"(b[0]), "=r"(b[1]) : "r"(addr));
}
__device__ __forceinline__ void mma16816(float c[4], const unsigned a[4], const unsigned b[2]) {
    asm volatile(
        "mma.sync.aligned.m16n8k16.row.col.f32.bf16.bf16.f32 "
        "{%0,%1,%2,%3}, {%4,%5,%6,%7}, {%8,%9}, {%0,%1,%2,%3};"
        : "+f"(c[0]), "+f"(c[1]), "+f"(c[2]), "+f"(c[3])
        : "r"(a[0]), "r"(a[1]), "r"(a[2]), "r"(a[3]), "r"(b[0]), "r"(b[1]));
}

// -------------------- epilogue functors ------------------------------------
struct EpiProj {  // bf16 out, add bias from d_bcat
    __device__ void operator()(int, int r, int c, float v0, float v1) const {
        bf162 p;
        p.x = __float2bfloat16(v0 + d_bcat[c]);
        p.y = __float2bfloat16(v1 + d_bcat[c + 1]);
        *(bf162*)&d_projbf[(size_t)r * NPROJ + c] = p;
    }
};
struct EpiO {     // bf16 attention out
    __device__ void operator()(int b, int r, int c, float v0, float v1) const {
        bf162 p; p.x = __float2bfloat16(v0); p.y = __float2bfloat16(v1);
        *(bf162*)&d_obf[((size_t)b * HW + r) * CHDIM + c] = p;
    }
};
struct EpiFinal { // out = gamma*(acc+bias) + x, fp32
    const float* x; const float* ob; const float* gm; float* out;
    __device__ void operator()(int, int r, int c, float v0, float v1) const {
        float g = gm[0];
        size_t off = (size_t)r * CC + c;
        float2 xv = *(const float2*)&x[off];
        float2 o;
        o.x = g * (v0 + ob[c])     + xv.x;
        o.y = g * (v1 + ob[c + 1]) + xv.y;
        *(float2*)&out[off] = o;
    }
};

// -------------------- high-occupancy bf16 GEMM -----------------------------
// C[M,N] (+epi) = A @ B.  Block tile 64x128x32, 8 warps (2x4), warp 32x32.
// 32-reg accumulators -> <=85 regs -> 3 CTAs/SM = 24 warps/SM (vs 16).
// AKM=false: A[m][k] (k contig).  AKM=true: A[k][m] (m contig).
// B always [k][n] (n contig).  AF32: A fp32 -> bf16 while staging.
// 2-stage smem, 1 syncthreads per K-chunk (round-10 proven loop).
template<bool AKM, bool AF32, class Epi>
__global__ __launch_bounds__(256, 3) void gemm_bf16(
    const void* __restrict__ Av, const bf16* __restrict__ B,
    int lda, int ldb, int K, size_t bsA, size_t bsB, Epi epi)
{
    constexpr int AST = AKM ? 72 : 40;    // smem row stride (halves)
    constexpr int ASZ = AKM ? 32 * 72 : 64 * 40;
    constexpr int BSZ = 32 * 136;
    __shared__ __align__(16) bf16 As[2 * ASZ];
    __shared__ __align__(16) bf16 Bs[2 * BSZ];

    const bf16*  A   = (const bf16*)Av;
    const float* A32 = (const float*)Av;
    const int bz = blockIdx.z;
    A   += (size_t)bz * bsA;
    A32 += (size_t)bz * bsA;
    B   += (size_t)bz * bsB;
    const int m0 = blockIdx.y * 64, n0 = blockIdx.x * 128;

    const int t = threadIdx.x;
    const unsigned lane = t & 31;
    const int w = t >> 5;
    const int wm0 = (w >> 2) * 32;     // 2 m-groups of 32
    const int wn0 = (w & 3) * 32;      // 4 n-groups of 32

    uint4 ra, rb[2];
    auto ldA = [&](int k0) {
        if (AF32) {
            int r = t >> 2, c = (t & 3) << 3;
            const float* p = A32 + (size_t)(m0 + r) * lda + k0 + c;
            float4 f0 = *(const float4*)p;
            float4 f1 = *(const float4*)(p + 4);
            bf162 h0 = __float22bfloat162_rn(make_float2(f0.x, f0.y));
            bf162 h1 = __float22bfloat162_rn(make_float2(f0.z, f0.w));
            bf162 h2 = __float22bfloat162_rn(make_float2(f1.x, f1.y));
            bf162 h3 = __float22bfloat162_rn(make_float2(f1.z, f1.w));
            ra.x = *(unsigned*)&h0; ra.y = *(unsigned*)&h1;
            ra.z = *(unsigned*)&h2; ra.w = *(unsigned*)&h3;
        } else if (!AKM) {
            int r = t >> 2, c = (t & 3) << 3;
            ra = *(const uint4*)(A + (size_t)(m0 + r) * lda + k0 + c);
        } else {
            int r = t >> 3, c = (t & 7) << 3;
            ra = *(const uint4*)(A + (size_t)(k0 + r) * lda + m0 + c);
        }
    };
    auto ldB = [&](int k0) {
        #pragma unroll
        for (int it = 0; it < 2; it++) {
            int e = it * 256 + t;
            int r = e >> 4, c = (e & 15) << 3;
            rb[it] = *(const uint4*)(B + (size_t)(k0 + r) * ldb + n0 + c);
        }
    };
    auto stAB = [&](int s) {
        bf16* Ap = As + s * ASZ;
        bf16* Bp = Bs + s * BSZ;
        if (!AKM) { int r = t >> 2, c = (t & 3) << 3; *(uint4*)&Ap[r * 40 + c] = ra; }
        else      { int r = t >> 3, c = (t & 7) << 3; *(uint4*)&Ap[r * 72 + c] = ra; }
        #pragma unroll
        for (int it = 0; it < 2; it++) {
            int e = it * 256 + t;
            int r = e >> 4, c = (e & 15) << 3;
            *(uint4*)&Bp[r * 136 + c] = rb[it];
        }
    };

    float cc[2][4][4] = {};
    const unsigned asb0 = smem_u32(As), bsb0 = smem_u32(Bs);
    const int nch = K / 32;

    ldA(0); ldB(0); stAB(0);

    for (int ch = 0; ch < nch; ch++) {
        __syncthreads();   // stage (ch&1) visible; all warps done with prev compute
        const bool more = (ch + 1 < nch);
        if (more) { ldA((ch + 1) * 32); ldB((ch + 1) * 32); }
        const unsigned asb = asb0 + (unsigned)((ch & 1) * ASZ * 2);
        const unsigned bsb = bsb0 + (unsigned)((ch & 1) * BSZ * 2);

        #pragma unroll
        for (int ks = 0; ks < 2; ks++) {
            const int kk = ks * 16;
            unsigned afr[2][4];
            #pragma unroll
            for (int mi = 0; mi < 2; mi++) {
                unsigned addr;
                if (!AKM) {
                    addr = asb + (unsigned)(((wm0 + mi * 16 + (lane & 15)) * 40
                                  + kk + ((lane >> 4) << 3)) * 2);
                    ldsm_x4(afr[mi], addr);
                } else {
                    addr = asb + (unsigned)(((kk + (lane & 7) + ((lane >> 4) << 3)) * 72
                                  + wm0 + mi * 16 + (((lane >> 3) & 1) << 3)) * 2);
                    ldsm_x4_t(afr[mi], addr);
                }
            }
            unsigned bfr[2][4];   // two n16 groups, each = two n8 frags
            #pragma unroll
            for (int nj = 0; nj < 2; nj++) {
                unsigned addr = bsb + (unsigned)(((kk + (lane & 15)) * 136
                                  + wn0 + nj * 16 + ((lane >> 4) << 3)) * 2);
                ldsm_x4_t(bfr[nj], addr);
            }
            #pragma unroll
            for (int mi = 0; mi < 2; mi++)
                #pragma unroll
                for (int nn = 0; nn < 4; nn++)
                    mma16816(cc[mi][nn], afr[mi], &bfr[nn >> 1][(nn & 1) * 2]);
        }

        if (more) stAB((ch + 1) & 1);   // other stage; safe after top barrier
    }

    #pragma unroll
    for (int mi = 0; mi < 2; mi++)
        #pragma unroll
        for (int nn = 0; nn < 4; nn++) {
            int r  = m0 + wm0 + mi * 16 + (int)(lane >> 2);
            int ci = n0 + wn0 + nn * 8 + (int)((lane & 3) << 1);
            epi(bz, r,     ci, cc[mi][nn][0], cc[mi][nn][1]);
            epi(bz, r + 8, ci, cc[mi][nn][2], cc[mi][nn][3]);
        }
}

// -------------------- dedicated e-GEMM: phi reuse over 8 j-tiles -----------
// (round-10 proven, unchanged — serves as control)
__global__ __launch_bounds__(256, 2) void k_egemm()
{
    constexpr int CSZ = 128 * 40;
    __shared__ __align__(16) bf16 As[2 * CSZ];
    __shared__ __align__(16) bf16 Bs[2][2 * CSZ];
    __shared__ float rs[128][4];

    const int jg = blockIdx.x;
    const int i0 = blockIdx.y * 128;
    const int bz = blockIdx.z;
    const bf16* Aph = d_phibf  + (size_t)bz * HWD * CFG;
    const bf16* Bth = d_projbf + (size_t)bz * HW * NPROJ;
    bf16* eb = d_ebf + ((size_t)bz * HWD + i0) * HW;

    const int t = threadIdx.x;
    const unsigned lane = t & 31;
    const int w = t >> 5;
    const int wm0 = (w >> 2) * 64;
    const int wn0 = (w & 3) * 32;
    const unsigned asb = smem_u32(As);

    #pragma unroll
    for (int ch = 0; ch < 2; ch++)
        #pragma unroll
        for (int it = 0; it < 2; it++) {
            int e = it * 256 + t;
            int r = e >> 2, c = (e & 3) << 3;
            *(uint4*)&As[ch * CSZ + r * 40 + c] =
                *(const uint4*)(Aph + (size_t)(i0 + r) * CFG + ch * 32 + c);
        }

    uint4 rB[4];
    auto ldB = [&](int jt) {
        const int j0 = jg * 1024 + jt * 128;
        #pragma unroll
        for (int ch = 0; ch < 2; ch++)
            #pragma unroll
            for (int it = 0; it < 2; it++) {
                int e = it * 256 + t;
                int r = e >> 2, c = (e & 3) << 3;
                rB[ch * 2 + it] =
                    *(const uint4*)(Bth + (size_t)(j0 + r) * NPROJ + ch * 32 + c);
            }
    };
    auto stB = [&](int s) {
        #pragma unroll
        for (int ch = 0; ch < 2; ch++)
            #pragma unroll
            for (int it = 0; it < 2; it++) {
                int e = it * 256 + t;
                int r = e >> 2, c = (e & 3) << 3;
                *(uint4*)&Bs[s][ch * CSZ + r * 40 + c] = rB[ch * 2 + it];
            }
    };

    float zp[4][2];
    #pragma unroll
    for (int mi = 0; mi < 4; mi++) { zp[mi][0] = 0.f; zp[mi][1] = 0.f; }

    ldB(0); stB(0);

    for (int jt = 0; jt < 8; jt++) {
        __syncthreads();
        const bool more = (jt + 1 < 8);
        if (more) ldB(jt + 1);

        const unsigned bsb = smem_u32(Bs[jt & 1]);
        float cc[4][4][4] = {};
        #pragma unroll
        for (int ch = 0; ch < 2; ch++) {
            const unsigned asc = asb + (unsigned)(ch * CSZ * 2);
            const unsigned bsc = bsb + (unsigned)(ch * CSZ * 2);
            #pragma unroll
            for (int ks = 0; ks < 2; ks++) {
                const int kk = ks * 16;
                unsigned afr[4][4];
                #pragma unroll
                for (int mi = 0; mi < 4; mi++)
                    ldsm_x4(afr[mi], asc + (unsigned)(((wm0 + mi * 16 + (lane & 15)) * 40
                                         + kk + ((lane >> 4) << 3)) * 2));
                unsigned bfr[4][2];
                #pragma unroll
                for (int ni = 0; ni < 4; ni++)
                    ldsm_x2(bfr[ni], bsc + (unsigned)(((wn0 + ni * 8 + (lane & 7)) * 40
                                         + kk + (((lane >> 3) & 1) << 3)) * 2));
                #pragma unroll
                for (int mi = 0; mi < 4; mi++)
                    #pragma unroll
                    for (int ni = 0; ni < 4; ni++)
                        mma16816(cc[mi][ni], afr[mi], bfr[ni]);
            }
        }

        const int jbase = jg * 1024 + jt * 128;
        #pragma unroll
        for (int mi = 0; mi < 4; mi++) {
            const int rl = wm0 + mi * 16 + (int)(lane >> 2);
            #pragma unroll
            for (int ni = 0; ni < 4; ni++) {
                const int cj = jbase + wn0 + ni * 8 + (int)((lane & 3) << 1);
                float e0 = __expf(cc[mi][ni][0]), e1 = __expf(cc[mi][ni][1]);
                float e2 = __expf(cc[mi][ni][2]), e3 = __expf(cc[mi][ni][3]);
                bf162 p; p.x = __float2bfloat16(e0); p.y = __float2bfloat16(e1);
                *(bf162*)&eb[(size_t)rl * HW + cj] = p;
                bf162 q; q.x = __float2bfloat16(e2); q.y = __float2bfloat16(e3);
                *(bf162*)&eb[(size_t)(rl + 8) * HW + cj] = q;
                zp[mi][0] += e0 + e1;
                zp[mi][1] += e2 + e3;
            }
        }

        if (more) stB((jt + 1) & 1);
    }

    #pragma unroll
    for (int mi = 0; mi < 4; mi++) {
        float rp0 = zp[mi][0], rp1 = zp[mi][1];
        rp0 += __shfl_xor_sync(0xffffffffu, rp0, 1);
        rp0 += __shfl_xor_sync(0xffffffffu, rp0, 2);
        rp1 += __shfl_xor_sync(0xffffffffu, rp1, 1);
        rp1 += __shfl_xor_sync(0xffffffffu, rp1, 2);
        if ((lane & 3) == 0) {
            int rl = wm0 + mi * 16 + (int)(lane >> 2);
            rs[rl][w & 3]     = rp0;
            rs[rl + 8][w & 3] = rp1;
        }
    }
    __syncthreads();
    if (t < 128) {
        float z = (rs[t][0] + rs[t][1]) + (rs[t][2] + rs[t][3]);
        d_part[((size_t)bz * HWD + i0 + t) * 4 + jg] = z;
    }
}

// -------------------- prep: weights/biases to bf16 --------------------------
__global__ __launch_bounds__(256) void k_cvt_w(
    const float* __restrict__ tw, const float* __restrict__ pw, const float* __restrict__ gw,
    const float* __restrict__ tb, const float* __restrict__ pb, const float* __restrict__ gb,
    const float* __restrict__ ow)
{
    int i = blockIdx.x * 256 + threadIdx.x;
    const int W1 = CC * NPROJ, W2 = W1 + CHDIM * CC;
    if (i < W1) {
        int r = i / NPROJ, c = i % NPROJ;
        float v = (c < 64) ? tw[r * 64 + c] : (c < 128) ? pw[r * 64 + c - 64]
                                            : gw[r * 256 + c - 128];
        d_wcat[i] = __float2bfloat16(v);
    } else if (i < W2) {
        int j = i - W1;
        d_owbf[j] = __float2bfloat16(ow[j]);
    } else if (i < W2 + NPROJ) {
        int c = i - W2;
        d_bcat[c] = (c < 64) ? tb[c] : (c < 128) ? pb[c - 64] : gb[c - 128];
    }
}

// -------------------- 2x2 maxpool of phi+g (bf16) ---------------------------
__global__ __launch_bounds__(256) void k_pool2() {
    int idx = blockIdx.x * 256 + threadIdx.x;
    if (idx >= BB * HWD * 160) return;
    int fp = idx % 160;
    int i  = (idx / 160) % HWD;
    int b  = idx / (160 * HWD);
    int h = i >> 5, w = i & 31;
    int col = 64 + fp * 2;
    size_t rb = ((size_t)b * HW + (size_t)(2 * h) * WWID + 2 * w) * NPROJ + col;
    bf162 v0 = *(const bf162*)&d_projbf[rb];
    bf162 v1 = *(const bf162*)&d_projbf[rb + NPROJ];
    bf162 v2 = *(const bf162*)&d_projbf[rb + (size_t)WWID * NPROJ];
    bf162 v3 = *(const bf162*)&d_projbf[rb + (size_t)(WWID + 1) * NPROJ];
    float mx = fmaxf(fmaxf(__bfloat162float(v0.x), __bfloat162float(v1.x)),
                     fmaxf(__bfloat162float(v2.x), __bfloat162float(v3.x)));
    float my = fmaxf(fmaxf(__bfloat162float(v0.y), __bfloat162float(v1.y)),
                     fmaxf(__bfloat162float(v2.y), __bfloat162float(v3.y)));
    bf162 o; o.x = __float2bfloat16(mx); o.y = __float2bfloat16(my);
    int f0 = fp * 2;
    if (f0 < 64) *(bf162*)&d_phibf[((size_t)b * HWD + i) * CFG + f0] = o;
    else         *(bf162*)&d_gbf  [((size_t)b * HWD + i) * CHDIM + (f0 - 64)] = o;
}

// -------------------- fused Z reduce + g scaling ----------------------------
__global__ __launch_bounds__(256) void k_zgscale() {
    int idx = blockIdx.x * 256 + threadIdx.x;     // bf162 pairs: 8*1024*128
    if (idx >= BB * HWD * 128) return;
    int row = idx >> 7;                           // (b*1024 + i)
    const float* p = &d_part[(size_t)row * 4];
    float iz = 1.0f / ((p[0] + p[1]) + (p[2] + p[3]));
    bf162 v = *(bf162*)&d_gbf[(size_t)idx * 2];
    v.x = __float2bfloat16(__bfloat162float(v.x) * iz);
    v.y = __float2bfloat16(__bfloat162float(v.y) * iz);
    *(bf162*)&d_gbf[(size_t)idx * 2] = v;
}

// -------------------- launch -----------------------------------------------
extern "C" void kernel_launch(void* const* d_in, const int* in_sizes, int n_in,
                              void* d_out, int out_size)
{
    const float* x  = (const float*)d_in[0];
    const float* tw = (const float*)d_in[1];
    const float* tb = (const float*)d_in[2];
    const float* pw = (const float*)d_in[3];
    const float* pb = (const float*)d_in[4];
    const float* gw = (const float*)d_in[5];
    const float* gb = (const float*)d_in[6];
    const float* ow = (const float*)d_in[7];
    const float* ob = (const float*)d_in[8];
    const float* gm = (const float*)d_in[9];
    float* out = (float*)d_out;

    void *p_wcat, *p_owbf, *p_gbf, *p_ebf, *p_obf;
    cudaGetSymbolAddress(&p_wcat, d_wcat);
    cudaGetSymbolAddress(&p_owbf, d_owbf);
    cudaGetSymbolAddress(&p_gbf,  d_gbf);
    cudaGetSymbolAddress(&p_ebf,  d_ebf);
    cudaGetSymbolAddress(&p_obf,  d_obf);

    // 0) weights to bf16 (x converted on the fly inside proj GEMM)
    k_cvt_w<<<(CC * NPROJ + CHDIM * CC + NPROJ + 255) / 256, 256>>>(tw, pw, gw, tb, pb, gb, ow);

    // 1) projections: [32768,512]fp32 @ [512,384] -> bf16 proj (+bias)
    gemm_bf16<false, true, EpiProj><<<dim3(NPROJ / 128, MROWS / 64, 1), 256>>>(
        x, (const bf16*)p_wcat, CC, NPROJ, CC, 0, 0, EpiProj{});

    // 2) 2x2 maxpool -> phi, g
    k_pool2<<<(BB * HWD * 160 + 255) / 256, 256>>>();

    // 3) e = exp(phi @ theta^T): phi reuse over 8 j-tiles per block
    k_egemm<<<dim3(HW / 1024, HWD / 128, BB), 256>>>();

    // 4) fused Z reduction + 1/Z fold into g rows
    k_zgscale<<<(BB * HWD * 128 + 255) / 256, 256>>>();

    // 5) o = e^T @ g' per batch: [4096,1024] @ [1024,256], A is [k][m]
    gemm_bf16<true, false, EpiO><<<dim3(CHDIM / 128, HW / 64, BB), 256>>>(
        p_ebf, (const bf16*)p_gbf, HW, CHDIM, HWD,
        (size_t)HWD * HW, (size_t)HWD * CHDIM, EpiO{});

    // 6) out = gamma*(o @ o3_w + b) + x: [32768,256] @ [256,512]
    EpiFinal ef{x, ob, gm, out};
    gemm_bf16<false, false, EpiFinal><<<dim3(CC / 128, MROWS / 64, 1), 256>>>(
        p_obf, (const bf16*)p_owbf, CHDIM, CC, CHDIM, 0, 0, ef);
}

// round 12
// speedup vs baseline: 1.0572x; 1.0572x over previous
#include <cuda_runtime.h>
#include <cuda_bf16.h>
#include <cstdint>
#include <math.h>

// Problem dims (fixed)
#define BB    8
#define HH    64
#define WWID  64
#define CC    512
#define CFG   64
#define CHDIM 256
#define HW    4096
#define HWD   1024
#define MROWS 32768          // BB*HW
#define NPROJ 384            // CFG + CFG + CHDIM

typedef __nv_bfloat16 bf16;
typedef __nv_bfloat162 bf162;

// -------------------- device scratch (BSS, allocation-free) ----------------
__device__ bf16  d_wcat [(size_t)CC * NPROJ];         // [theta|phi|g] weights
__device__ bf16  d_owbf [(size_t)CHDIM * CC];         // o3 weights
__device__ float d_bcat [NPROJ];                      // [theta|phi|g] biases
__device__ bf16  d_thetabf[(size_t)MROWS * CFG];      // theta, compact [m][64]
__device__ bf16  d_phibf[(size_t)BB * HWD * CFG];
__device__ bf16  d_gbf  [(size_t)BB * HWD * CHDIM];   // pooled g, scaled by 1/Z
__device__ bf16  d_ebf  [(size_t)BB * HWD * HW];      // e = exp(s), unnormalized
__device__ float d_part [(size_t)BB * HWD * 4];       // per-(row, jgroup) partials
__device__ bf16  d_obf  [(size_t)MROWS * CHDIM];      // attention out

// -------------------- PTX helpers -----------------------------------------
__device__ __forceinline__ unsigned smem_u32(const void* p) {
    return (unsigned)__cvta_generic_to_shared(p);
}
__device__ __forceinline__ void ldsm_x4(unsigned a[4], unsigned addr) {
    asm volatile("ldmatrix.sync.aligned.m8n8.x4.shared.b16 {%0,%1,%2,%3}, [%4];"
        : "=r"(a[0]), "=r"(a[1]), "=r"(a[2]), "=r"(a[3]) : "r"(addr));
}
__device__ __forceinline__ void ldsm_x4_t(unsigned a[4], unsigned addr) {
    asm volatile("ldmatrix.sync.aligned.m8n8.x4.trans.shared.b16 {%0,%1,%2,%3}, [%4];"
        : "=r"(a[0]), "=r"(a[1]), "=r"(a[2]), "=r"(a[3]) : "r"(addr));
}
__device__ __forceinline__ void ldsm_x2(unsigned b[2], unsigned addr) {
    asm volatile("ldmatrix.sync.aligned.m8n8.x2.shared.b16 {%0,%1}, [%2];"
        : "=r"(b[0]), "=r"(b[1]) : "r"(addr));
}
__device__ __forceinline__ void ldsm_x2_t(unsigned b[2], unsigned addr) {
    asm volatile("ldmatrix.sync.aligned.m8n8.x2.trans.shared.b16 {%0,%1}, [%2];"
        : "=r"(b[0]), "=r"(b[1]) : "r"(addr));
}
__device__ __forceinline__ void mma16816(float c[4], const unsigned a[4], const unsigned b[2]) {
    asm volatile(
        "mma.sync.aligned.m16n8k16.row.col.f32.bf16.bf16.f32 "
        "{%0,%1,%2,%3}, {%4,%5,%6,%7}, {%8,%9}, {%0,%1,%2,%3};"
        : "+f"(c[0]), "+f"(c[1]), "+f"(c[2]), "+f"(c[3])
        : "r"(a[0]), "r"(a[1]), "r"(a[2]), "r"(a[3]), "r"(b[0]), "r"(b[1]));
}

// -------------------- epilogue functors ------------------------------------
struct EpiO {     // bf16 attention out
    __device__ void operator()(int b, int r, int c, float v0, float v1) const {
        bf162 p; p.x = __float2bfloat16(v0); p.y = __float2bfloat16(v1);
        *(bf162*)&d_obf[((size_t)b * HW + r) * CHDIM + c] = p;
    }
};
struct EpiFinal { // out = gamma*(acc+bias) + x, fp32
    const float* x; const float* ob; const float* gm; float* out;
    __device__ void operator()(int, int r, int c, float v0, float v1) const {
        float g = gm[0];
        size_t off = (size_t)r * CC + c;
        float2 xv = *(const float2*)&x[off];
        float2 o;
        o.x = g * (v0 + ob[c])     + xv.x;
        o.y = g * (v1 + ob[c + 1]) + xv.y;
        *(float2*)&out[off] = o;
    }
};

// -------------------- bf16 GEMM: 2-stage smem, 1 sync per chunk ------------
// (round-10 proven, verbatim)
template<bool AKM, bool BNK, bool AF32, class Epi>
__global__ __launch_bounds__(256, 2) void gemm_bf16(
    const void* __restrict__ Av, const bf16* __restrict__ B,
    int lda, int ldb, int K, size_t bsA, size_t bsB, Epi epi)
{
    constexpr int AST = AKM ? 136 : 40;
    constexpr int ASZ = AKM ? 32 * 136 : 128 * 40;
    constexpr int BST = BNK ? 40 : 136;
    constexpr int BSZ = BNK ? 128 * 40 : 32 * 136;
    __shared__ __align__(16) bf16 As[2 * ASZ];
    __shared__ __align__(16) bf16 Bs[2 * BSZ];

    const bf16*  A   = (const bf16*)Av;
    const float* A32 = (const float*)Av;
    const int bz = blockIdx.z;
    A   += (size_t)bz * bsA;
    A32 += (size_t)bz * bsA;
    B   += (size_t)bz * bsB;
    const int m0 = blockIdx.y * 128, n0 = blockIdx.x * 128;

    const int t = threadIdx.x;
    const unsigned lane = t & 31;
    const int w = t >> 5;
    const int wm0 = (w >> 2) * 64;
    const int wn0 = (w & 3) * 32;

    uint4 ra[2], rb[2];
    auto ldA = [&](int k0) {
        #pragma unroll
        for (int it = 0; it < 2; it++) {
            int e = it * 256 + t;
            if (AF32) {
                int r = e >> 2, c = (e & 3) << 3;
                const float* p = A32 + (size_t)(m0 + r) * lda + k0 + c;
                float4 f0 = *(const float4*)p;
                float4 f1 = *(const float4*)(p + 4);
                bf162 h0 = __float22bfloat162_rn(make_float2(f0.x, f0.y));
                bf162 h1 = __float22bfloat162_rn(make_float2(f0.z, f0.w));
                bf162 h2 = __float22bfloat162_rn(make_float2(f1.x, f1.y));
                bf162 h3 = __float22bfloat162_rn(make_float2(f1.z, f1.w));
                ra[it].x = *(unsigned*)&h0; ra[it].y = *(unsigned*)&h1;
                ra[it].z = *(unsigned*)&h2; ra[it].w = *(unsigned*)&h3;
            } else if (!AKM) {
                int r = e >> 2, c = (e & 3) << 3;
                ra[it] = *(const uint4*)(A + (size_t)(m0 + r) * lda + k0 + c);
            } else {
                int r = e >> 4, c = (e & 15) << 3;
                ra[it] = *(const uint4*)(A + (size_t)(k0 + r) * lda + m0 + c);
            }
        }
    };
    auto ldB = [&](int k0) {
        #pragma unroll
        for (int it = 0; it < 2; it++) {
            int e = it * 256 + t;
            if (BNK) { int r = e >> 2, c = (e & 3) << 3;
                rb[it] = *(const uint4*)(B + (size_t)(n0 + r) * ldb + k0 + c); }
            else     { int r = e >> 4, c = (e & 15) << 3;
                rb[it] = *(const uint4*)(B + (size_t)(k0 + r) * ldb + n0 + c); }
        }
    };
    auto stAB = [&](int s) {
        bf16* Ap = As + s * ASZ;
        bf16* Bp = Bs + s * BSZ;
        #pragma unroll
        for (int it = 0; it < 2; it++) {
            int e = it * 256 + t;
            if (!AKM) { int r = e >> 2, c = (e & 3) << 3; *(uint4*)&Ap[r * 40 + c] = ra[it]; }
            else      { int r = e >> 4, c = (e & 15) << 3; *(uint4*)&Ap[r * 136 + c] = ra[it]; }
            if (BNK)  { int r = e >> 2, c = (e & 3) << 3; *(uint4*)&Bp[r * 40 + c] = rb[it]; }
            else      { int r = e >> 4, c = (e & 15) << 3; *(uint4*)&Bp[r * 136 + c] = rb[it]; }
        }
    };

    float cc[4][4][4] = {};
    const unsigned asb0 = smem_u32(As), bsb0 = smem_u32(Bs);
    const int nch = K / 32;

    ldA(0); ldB(0); stAB(0);

    for (int ch = 0; ch < nch; ch++) {
        __syncthreads();
        const bool more = (ch + 1 < nch);
        if (more) { ldA((ch + 1) * 32); ldB((ch + 1) * 32); }
        const unsigned asb = asb0 + (unsigned)((ch & 1) * ASZ * 2);
        const unsigned bsb = bsb0 + (unsigned)((ch & 1) * BSZ * 2);

        #pragma unroll
        for (int ks = 0; ks < 2; ks++) {
            const int kk = ks * 16;
            unsigned afr[4][4];
            #pragma unroll
            for (int mi = 0; mi < 4; mi++) {
                unsigned addr;
                if (!AKM) {
                    addr = asb + (unsigned)(((wm0 + mi * 16 + (lane & 15)) * AST
                                  + kk + ((lane >> 4) << 3)) * 2);
                    ldsm_x4(afr[mi], addr);
                } else {
                    addr = asb + (unsigned)(((kk + (lane & 7) + ((lane >> 4) << 3)) * AST
                                  + wm0 + mi * 16 + (((lane >> 3) & 1) << 3)) * 2);
                    ldsm_x4_t(afr[mi], addr);
                }
            }
            unsigned bfr[4][2];
            #pragma unroll
            for (int ni = 0; ni < 4; ni++) {
                unsigned addr;
                if (!BNK) {
                    addr = bsb + (unsigned)(((kk + (lane & 15)) * BST + wn0 + ni * 8) * 2);
                    ldsm_x2_t(bfr[ni], addr);
                } else {
                    addr = bsb + (unsigned)(((wn0 + ni * 8 + (lane & 7)) * BST
                                  + kk + (((lane >> 3) & 1) << 3)) * 2);
                    ldsm_x2(bfr[ni], addr);
                }
            }
            #pragma unroll
            for (int mi = 0; mi < 4; mi++)
                #pragma unroll
                for (int ni = 0; ni < 4; ni++)
                    mma16816(cc[mi][ni], afr[mi], bfr[ni]);
        }

        if (more) stAB((ch + 1) & 1);
    }

    #pragma unroll
    for (int mi = 0; mi < 4; mi++)
        #pragma unroll
        for (int ni = 0; ni < 4; ni++) {
            int r  = m0 + wm0 + mi * 16 + (int)(lane >> 2);
            int ci = n0 + wn0 + ni * 8 + (int)((lane & 3) << 1);
            epi(bz, r,     ci, cc[mi][ni][0], cc[mi][ni][1]);
            epi(bz, r + 8, ci, cc[mi][ni][2], cc[mi][ni][3]);
        }
}

// -------------------- proj GEMM with fused bias + maxpool ------------------
// C[m, n0:n0+128] = x_fp32[m, :] @ wcat + bias.  Tile 128x128, K=512.
// A 128-row tile = exactly 2 image rows -> 2x2 pool is tile-local:
// pooled(wp) = max over local rows {2wp, 2wp+1, 64+2wp, 65+2wp}.
// nb=0: cols 0-63 theta -> d_thetabf (compact ld=64); cols 64-127 phi -> pool.
// nb=1/2: g columns -> pool into d_gbf.
__global__ __launch_bounds__(256, 2) void k_proj(const float* __restrict__ X,
                                                 const bf16* __restrict__ Bw)
{
    constexpr int ASZ = 128 * 40;
    constexpr int BSZ = 32 * 136;
    __shared__ __align__(16) bf16 smbuf[2 * ASZ + 2 * BSZ];   // >= 128*136
    bf16* As = smbuf;
    bf16* Bs = smbuf + 2 * ASZ;

    const int nb = blockIdx.x;             // 0..2
    const int m0 = blockIdx.y * 128;
    const int n0 = nb * 128;

    const int t = threadIdx.x;
    const unsigned lane = t & 31;
    const int w = t >> 5;
    const int wm0 = (w >> 2) * 64;
    const int wn0 = (w & 3) * 32;

    uint4 ra[2], rb[2];
    auto ldA = [&](int k0) {
        #pragma unroll
        for (int it = 0; it < 2; it++) {
            int e = it * 256 + t;
            int r = e >> 2, c = (e & 3) << 3;
            const float* p = X + (size_t)(m0 + r) * CC + k0 + c;
            float4 f0 = *(const float4*)p;
            float4 f1 = *(const float4*)(p + 4);
            bf162 h0 = __float22bfloat162_rn(make_float2(f0.x, f0.y));
            bf162 h1 = __float22bfloat162_rn(make_float2(f0.z, f0.w));
            bf162 h2 = __float22bfloat162_rn(make_float2(f1.x, f1.y));
            bf162 h3 = __float22bfloat162_rn(make_float2(f1.z, f1.w));
            ra[it].x = *(unsigned*)&h0; ra[it].y = *(unsigned*)&h1;
            ra[it].z = *(unsigned*)&h2; ra[it].w = *(unsigned*)&h3;
        }
    };
    auto ldB = [&](int k0) {
        #pragma unroll
        for (int it = 0; it < 2; it++) {
            int e = it * 256 + t;
            int r = e >> 4, c = (e & 15) << 3;
            rb[it] = *(const uint4*)(Bw + (size_t)(k0 + r) * NPROJ + n0 + c);
        }
    };
    auto stAB = [&](int s) {
        bf16* Ap = As + s * ASZ;
        bf16* Bp = Bs + s * BSZ;
        #pragma unroll
        for (int it = 0; it < 2; it++) {
            int e = it * 256 + t;
            { int r = e >> 2, c = (e & 3) << 3; *(uint4*)&Ap[r * 40 + c] = ra[it]; }
            { int r = e >> 4, c = (e & 15) << 3; *(uint4*)&Bp[r * 136 + c] = rb[it]; }
        }
    };

    float cc[4][4][4] = {};
    const unsigned asb0 = smem_u32(As), bsb0 = smem_u32(Bs);

    ldA(0); ldB(0); stAB(0);

    for (int ch = 0; ch < 16; ch++) {                  // K=512
        __syncthreads();
        const bool more = (ch + 1 < 16);
        if (more) { ldA((ch + 1) * 32); ldB((ch + 1) * 32); }
        const unsigned asb = asb0 + (unsigned)((ch & 1) * ASZ * 2);
        const unsigned bsb = bsb0 + (unsigned)((ch & 1) * BSZ * 2);

        #pragma unroll
        for (int ks = 0; ks < 2; ks++) {
            const int kk = ks * 16;
            unsigned afr[4][4];
            #pragma unroll
            for (int mi = 0; mi < 4; mi++)
                ldsm_x4(afr[mi], asb + (unsigned)(((wm0 + mi * 16 + (lane & 15)) * 40
                                     + kk + ((lane >> 4) << 3)) * 2));
            unsigned bfr[4][2];
            #pragma unroll
            for (int ni = 0; ni < 4; ni++)
                ldsm_x2_t(bfr[ni], bsb + (unsigned)(((kk + (lane & 15)) * 136
                                       + wn0 + ni * 8) * 2));
            #pragma unroll
            for (int mi = 0; mi < 4; mi++)
                #pragma unroll
                for (int ni = 0; ni < 4; ni++)
                    mma16816(cc[mi][ni], afr[mi], bfr[ni]);
        }

        if (more) stAB((ch + 1) & 1);
    }

    // ---- stage biased bf16 tile into smem [128][136] ----
    __syncthreads();                       // all compute smem reads done
    #pragma unroll
    for (int mi = 0; mi < 4; mi++)
        #pragma unroll
        for (int ni = 0; ni < 4; ni++) {
            int rl = wm0 + mi * 16 + (int)(lane >> 2);
            int ci = wn0 + ni * 8 + (int)((lane & 3) << 1);
            float b0 = d_bcat[n0 + ci], b1 = d_bcat[n0 + ci + 1];
            bf162 p;
            p.x = __float2bfloat16(cc[mi][ni][0] + b0);
            p.y = __float2bfloat16(cc[mi][ni][1] + b1);
            *(bf162*)&smbuf[rl * 136 + ci] = p;
            bf162 q;
            q.x = __float2bfloat16(cc[mi][ni][2] + b0);
            q.y = __float2bfloat16(cc[mi][ni][3] + b1);
            *(bf162*)&smbuf[(rl + 8) * 136 + ci] = q;
        }
    __syncthreads();

    const int b     = m0 >> 12;                        // batch
    const int ibase = ((m0 & 4095) >> 7) << 5;         // pooled row base
    auto pool4 = [&](int wp, int col) -> bf16 {
        float v0 = __bfloat162float(smbuf[(2 * wp) * 136 + col]);
        float v1 = __bfloat162float(smbuf[(2 * wp + 1) * 136 + col]);
        float v2 = __bfloat162float(smbuf[(64 + 2 * wp) * 136 + col]);
        float v3 = __bfloat162float(smbuf[(65 + 2 * wp) * 136 + col]);
        return __float2bfloat16(fmaxf(fmaxf(v0, v1), fmaxf(v2, v3)));
    };

    if (nb == 0) {
        // theta: cols 0..63 -> compact d_thetabf
        {
            const int r = t >> 1, half = t & 1;
            const unsigned* sp = (const unsigned*)&smbuf[r * 136 + half * 32];
            unsigned* gp = (unsigned*)&d_thetabf[(size_t)(m0 + r) * CFG + half * 32];
            #pragma unroll
            for (int k = 0; k < 16; k++) gp[k] = sp[k];
        }
        // phi: cols 64..127 -> 2x2 pooled
        #pragma unroll
        for (int k = 0; k < 8; k++) {
            int o = k * 256 + t;                       // 2048 outputs
            int wp = o >> 6, c = o & 63;
            d_phibf[((size_t)b * HWD + ibase + wp) * CFG + c] = pool4(wp, 64 + c);
        }
    } else {
        // g: 128 cols -> 2x2 pooled
        #pragma unroll
        for (int k = 0; k < 16; k++) {
            int o = k * 256 + t;                       // 4096 outputs
            int wp = o >> 7, c = o & 127;
            d_gbf[((size_t)b * HWD + ibase + wp) * CHDIM + (nb - 1) * 128 + c]
                = pool4(wp, c);
        }
    }
}

// -------------------- dedicated e-GEMM: phi reuse over 8 j-tiles -----------
// (round-10 proven; theta now read compact from d_thetabf, ld=64)
__global__ __launch_bounds__(256, 2) void k_egemm()
{
    constexpr int CSZ = 128 * 40;
    __shared__ __align__(16) bf16 As[2 * CSZ];
    __shared__ __align__(16) bf16 Bs[2][2 * CSZ];
    __shared__ float rs[128][4];

    const int jg = blockIdx.x;
    const int i0 = blockIdx.y * 128;
    const int bz = blockIdx.z;
    const bf16* Aph = d_phibf   + (size_t)bz * HWD * CFG;
    const bf16* Bth = d_thetabf + (size_t)bz * HW * CFG;
    bf16* eb = d_ebf + ((size_t)bz * HWD + i0) * HW;

    const int t = threadIdx.x;
    const unsigned lane = t & 31;
    const int w = t >> 5;
    const int wm0 = (w >> 2) * 64;
    const int wn0 = (w & 3) * 32;
    const unsigned asb = smem_u32(As);

    #pragma unroll
    for (int ch = 0; ch < 2; ch++)
        #pragma unroll
        for (int it = 0; it < 2; it++) {
            int e = it * 256 + t;
            int r = e >> 2, c = (e & 3) << 3;
            *(uint4*)&As[ch * CSZ + r * 40 + c] =
                *(const uint4*)(Aph + (size_t)(i0 + r) * CFG + ch * 32 + c);
        }

    uint4 rB[4];
    auto ldB = [&](int jt) {
        const int j0 = jg * 1024 + jt * 128;
        #pragma unroll
        for (int ch = 0; ch < 2; ch++)
            #pragma unroll
            for (int it = 0; it < 2; it++) {
                int e = it * 256 + t;
                int r = e >> 2, c = (e & 3) << 3;
                rB[ch * 2 + it] =
                    *(const uint4*)(Bth + (size_t)(j0 + r) * CFG + ch * 32 + c);
            }
    };
    auto stB = [&](int s) {
        #pragma unroll
        for (int ch = 0; ch < 2; ch++)
            #pragma unroll
            for (int it = 0; it < 2; it++) {
                int e = it * 256 + t;
                int r = e >> 2, c = (e & 3) << 3;
                *(uint4*)&Bs[s][ch * CSZ + r * 40 + c] = rB[ch * 2 + it];
            }
    };

    float zp[4][2];
    #pragma unroll
    for (int mi = 0; mi < 4; mi++) { zp[mi][0] = 0.f; zp[mi][1] = 0.f; }

    ldB(0); stB(0);

    for (int jt = 0; jt < 8; jt++) {
        __syncthreads();
        const bool more = (jt + 1 < 8);
        if (more) ldB(jt + 1);

        const unsigned bsb = smem_u32(Bs[jt & 1]);
        float cc[4][4][4] = {};
        #pragma unroll
        for (int ch = 0; ch < 2; ch++) {
            const unsigned asc = asb + (unsigned)(ch * CSZ * 2);
            const unsigned bsc = bsb + (unsigned)(ch * CSZ * 2);
            #pragma unroll
            for (int ks = 0; ks < 2; ks++) {
                const int kk = ks * 16;
                unsigned afr[4][4];
                #pragma unroll
                for (int mi = 0; mi < 4; mi++)
                    ldsm_x4(afr[mi], asc + (unsigned)(((wm0 + mi * 16 + (lane & 15)) * 40
                                         + kk + ((lane >> 4) << 3)) * 2));
                unsigned bfr[4][2];
                #pragma unroll
                for (int ni = 0; ni < 4; ni++)
                    ldsm_x2(bfr[ni], bsc + (unsigned)(((wn0 + ni * 8 + (lane & 7)) * 40
                                         + kk + (((lane >> 3) & 1) << 3)) * 2));
                #pragma unroll
                for (int mi = 0; mi < 4; mi++)
                    #pragma unroll
                    for (int ni = 0; ni < 4; ni++)
                        mma16816(cc[mi][ni], afr[mi], bfr[ni]);
            }
        }

        const int jbase = jg * 1024 + jt * 128;
        #pragma unroll
        for (int mi = 0; mi < 4; mi++) {
            const int rl = wm0 + mi * 16 + (int)(lane >> 2);
            #pragma unroll
            for (int ni = 0; ni < 4; ni++) {
                const int cj = jbase + wn0 + ni * 8 + (int)((lane & 3) << 1);
                float e0 = __expf(cc[mi][ni][0]), e1 = __expf(cc[mi][ni][1]);
                float e2 = __expf(cc[mi][ni][2]), e3 = __expf(cc[mi][ni][3]);
                bf162 p; p.x = __float2bfloat16(e0); p.y = __float2bfloat16(e1);
                *(bf162*)&eb[(size_t)rl * HW + cj] = p;
                bf162 q; q.x = __float2bfloat16(e2); q.y = __float2bfloat16(e3);
                *(bf162*)&eb[(size_t)(rl + 8) * HW + cj] = q;
                zp[mi][0] += e0 + e1;
                zp[mi][1] += e2 + e3;
            }
        }

        if (more) stB((jt + 1) & 1);
    }

    #pragma unroll
    for (int mi = 0; mi < 4; mi++) {
        float rp0 = zp[mi][0], rp1 = zp[mi][1];
        rp0 += __shfl_xor_sync(0xffffffffu, rp0, 1);
        rp0 += __shfl_xor_sync(0xffffffffu, rp0, 2);
        rp1 += __shfl_xor_sync(0xffffffffu, rp1, 1);
        rp1 += __shfl_xor_sync(0xffffffffu, rp1, 2);
        if ((lane & 3) == 0) {
            int rl = wm0 + mi * 16 + (int)(lane >> 2);
            rs[rl][w & 3]     = rp0;
            rs[rl + 8][w & 3] = rp1;
        }
    }
    __syncthreads();
    if (t < 128) {
        float z = (rs[t][0] + rs[t][1]) + (rs[t][2] + rs[t][3]);
        d_part[((size_t)bz * HWD + i0 + t) * 4 + jg] = z;
    }
}

// -------------------- prep: weights/biases to bf16 --------------------------
__global__ __launch_bounds__(256) void k_cvt_w(
    const float* __restrict__ tw, const float* __restrict__ pw, const float* __restrict__ gw,
    const float* __restrict__ tb, const float* __restrict__ pb, const float* __restrict__ gb,
    const float* __restrict__ ow)
{
    int i = blockIdx.x * 256 + threadIdx.x;
    const int W1 = CC * NPROJ, W2 = W1 + CHDIM * CC;
    if (i < W1) {
        int r = i / NPROJ, c = i % NPROJ;
        float v = (c < 64) ? tw[r * 64 + c] : (c < 128) ? pw[r * 64 + c - 64]
                                            : gw[r * 256 + c - 128];
        d_wcat[i] = __float2bfloat16(v);
    } else if (i < W2) {
        int j = i - W1;
        d_owbf[j] = __float2bfloat16(ow[j]);
    } else if (i < W2 + NPROJ) {
        int c = i - W2;
        d_bcat[c] = (c < 64) ? tb[c] : (c < 128) ? pb[c - 64] : gb[c - 128];
    }
}

// -------------------- fused Z reduce + g scaling ----------------------------
__global__ __launch_bounds__(256) void k_zgscale() {
    int idx = blockIdx.x * 256 + threadIdx.x;     // bf162 pairs: 8*1024*128
    if (idx >= BB * HWD * 128) return;
    int row = idx >> 7;                           // (b*1024 + i)
    const float* p = &d_part[(size_t)row * 4];
    float iz = 1.0f / ((p[0] + p[1]) + (p[2] + p[3]));
    bf162 v = *(bf162*)&d_gbf[(size_t)idx * 2];
    v.x = __float2bfloat16(__bfloat162float(v.x) * iz);
    v.y = __float2bfloat16(__bfloat162float(v.y) * iz);
    *(bf162*)&d_gbf[(size_t)idx * 2] = v;
}

// -------------------- launch -----------------------------------------------
extern "C" void kernel_launch(void* const* d_in, const int* in_sizes, int n_in,
                              void* d_out, int out_size)
{
    const float* x  = (const float*)d_in[0];
    const float* tw = (const float*)d_in[1];
    const float* tb = (const float*)d_in[2];
    const float* pw = (const float*)d_in[3];
    const float* pb = (const float*)d_in[4];
    const float* gw = (const float*)d_in[5];
    const float* gb = (const float*)d_in[6];
    const float* ow = (const float*)d_in[7];
    const float* ob = (const float*)d_in[8];
    const float* gm = (const float*)d_in[9];
    float* out = (float*)d_out;

    void *p_wcat, *p_owbf, *p_gbf, *p_ebf, *p_obf;
    cudaGetSymbolAddress(&p_wcat, d_wcat);
    cudaGetSymbolAddress(&p_owbf, d_owbf);
    cudaGetSymbolAddress(&p_gbf,  d_gbf);
    cudaGetSymbolAddress(&p_ebf,  d_ebf);
    cudaGetSymbolAddress(&p_obf,  d_obf);

    // 0) weights to bf16 (x converted on the fly inside proj GEMM)
    k_cvt_w<<<(CC * NPROJ + CHDIM * CC + NPROJ + 255) / 256, 256>>>(tw, pw, gw, tb, pb, gb, ow);

    // 1) projections + bias + fused 2x2 maxpool -> theta (compact), phi, g
    k_proj<<<dim3(3, MROWS / 128), 256>>>(x, (const bf16*)p_wcat);

    // 2) e = exp(phi @ theta^T): phi reuse over 8 j-tiles per block
    k_egemm<<<dim3(HW / 1024, HWD / 128, BB), 256>>>();

    // 3) fused Z reduction + 1/Z fold into g rows
    k_zgscale<<<(BB * HWD * 128 + 255) / 256, 256>>>();

    // 4) o = e^T @ g' per batch: [4096,1024] @ [1024,256], A is [k][m]
    gemm_bf16<true, false, false, EpiO><<<dim3(CHDIM / 128, HW / 128, BB), 256>>>(
        p_ebf, (const bf16*)p_gbf, HW, CHDIM, HWD,
        (size_t)HWD * HW, (size_t)HWD * CHDIM, EpiO{});

    // 5) out = gamma*(o @ o3_w + b) + x: [32768,256] @ [256,512]
    EpiFinal ef{x, ob, gm, out};
    gemm_bf16<false, false, false, EpiFinal><<<dim3(CC / 128, MROWS / 128, 1), 256>>>(
        p_obf, (const bf16*)p_owbf, CHDIM, CC, CHDIM, 0, 0, ef);
}

// round 13
// speedup vs baseline: 1.0752x; 1.0171x over previous
#include <cuda_runtime.h>
#include <cuda_bf16.h>
#include <cstdint>
#include <math.h>

// Problem dims (fixed)
#define BB    8
#define HH    64
#define WWID  64
#define CC    512
#define CFG   64
#define CHDIM 256
#define HW    4096
#define HWD   1024
#define MROWS 32768          // BB*HW
#define NPROJ 384            // CFG + CFG + CHDIM

typedef __nv_bfloat16 bf16;
typedef __nv_bfloat162 bf162;

// -------------------- device scratch (BSS, allocation-free) ----------------
__device__ bf16  d_wcat [(size_t)CC * NPROJ];         // [theta|phi|g] weights
__device__ bf16  d_owbf [(size_t)CHDIM * CC];         // o3 weights
__device__ float d_bcat [NPROJ];                      // [theta|phi|g] biases
__device__ bf16  d_thetabf[(size_t)MROWS * CFG];      // theta, compact [m][64]
__device__ bf16  d_phibf[(size_t)BB * HWD * CFG];
__device__ bf16  d_gbf  [(size_t)BB * HWD * CHDIM];   // pooled g, scaled by 1/Z
__device__ bf16  d_ebf  [(size_t)BB * HWD * HW];      // e = exp(s), unnormalized
__device__ float d_part [(size_t)BB * HWD * 4];       // per-(row, jgroup) partials
__device__ bf16  d_obf  [(size_t)MROWS * CHDIM];      // attention out

// -------------------- PTX helpers -----------------------------------------
__device__ __forceinline__ unsigned smem_u32(const void* p) {
    return (unsigned)__cvta_generic_to_shared(p);
}
__device__ __forceinline__ void ldsm_x4(unsigned a[4], unsigned addr) {
    asm volatile("ldmatrix.sync.aligned.m8n8.x4.shared.b16 {%0,%1,%2,%3}, [%4];"
        : "=r"(a[0]), "=r"(a[1]), "=r"(a[2]), "=r"(a[3]) : "r"(addr));
}
__device__ __forceinline__ void ldsm_x4_t(unsigned a[4], unsigned addr) {
    asm volatile("ldmatrix.sync.aligned.m8n8.x4.trans.shared.b16 {%0,%1,%2,%3}, [%4];"
        : "=r"(a[0]), "=r"(a[1]), "=r"(a[2]), "=r"(a[3]) : "r"(addr));
}
__device__ __forceinline__ void ldsm_x2(unsigned b[2], unsigned addr) {
    asm volatile("ldmatrix.sync.aligned.m8n8.x2.shared.b16 {%0,%1}, [%2];"
        : "=r"(b[0]), "=r"(b[1]) : "r"(addr));
}
__device__ __forceinline__ void ldsm_x2_t(unsigned b[2], unsigned addr) {
    asm volatile("ldmatrix.sync.aligned.m8n8.x2.trans.shared.b16 {%0,%1}, [%2];"
        : "=r"(b[0]), "=r"(b[1]) : "r"(addr));
}
__device__ __forceinline__ void mma16816(float c[4], const unsigned a[4], const unsigned b[2]) {
    asm volatile(
        "mma.sync.aligned.m16n8k16.row.col.f32.bf16.bf16.f32 "
        "{%0,%1,%2,%3}, {%4,%5,%6,%7}, {%8,%9}, {%0,%1,%2,%3};"
        : "+f"(c[0]), "+f"(c[1]), "+f"(c[2]), "+f"(c[3])
        : "r"(a[0]), "r"(a[1]), "r"(a[2]), "r"(a[3]), "r"(b[0]), "r"(b[1]));
}

// -------------------- epilogue functors ------------------------------------
struct EpiO {     // bf16 attention out
    __device__ void operator()(int b, int r, int c, float v0, float v1) const {
        bf162 p; p.x = __float2bfloat16(v0); p.y = __float2bfloat16(v1);
        *(bf162*)&d_obf[((size_t)b * HW + r) * CHDIM + c] = p;
    }
};
struct EpiFinal { // out = gamma*(acc+bias) + x, fp32
    const float* x; const float* ob; const float* gm; float* out;
    __device__ void operator()(int, int r, int c, float v0, float v1) const {
        float g = gm[0];
        size_t off = (size_t)r * CC + c;
        float2 xv = *(const float2*)&x[off];
        float2 o;
        o.x = g * (v0 + ob[c])     + xv.x;
        o.y = g * (v1 + ob[c + 1]) + xv.y;
        *(float2*)&out[off] = o;
    }
};

// -------------------- bf16 GEMM: 2-stage smem, 1 sync per chunk ------------
// (round-10 proven, verbatim)
template<bool AKM, bool BNK, bool AF32, class Epi>
__global__ __launch_bounds__(256, 2) void gemm_bf16(
    const void* __restrict__ Av, const bf16* __restrict__ B,
    int lda, int ldb, int K, size_t bsA, size_t bsB, Epi epi)
{
    constexpr int AST = AKM ? 136 : 40;
    constexpr int ASZ = AKM ? 32 * 136 : 128 * 40;
    constexpr int BST = BNK ? 40 : 136;
    constexpr int BSZ = BNK ? 128 * 40 : 32 * 136;
    __shared__ __align__(16) bf16 As[2 * ASZ];
    __shared__ __align__(16) bf16 Bs[2 * BSZ];

    const bf16*  A   = (const bf16*)Av;
    const float* A32 = (const float*)Av;
    const int bz = blockIdx.z;
    A   += (size_t)bz * bsA;
    A32 += (size_t)bz * bsA;
    B   += (size_t)bz * bsB;
    const int m0 = blockIdx.y * 128, n0 = blockIdx.x * 128;

    const int t = threadIdx.x;
    const unsigned lane = t & 31;
    const int w = t >> 5;
    const int wm0 = (w >> 2) * 64;
    const int wn0 = (w & 3) * 32;

    uint4 ra[2], rb[2];
    auto ldA = [&](int k0) {
        #pragma unroll
        for (int it = 0; it < 2; it++) {
            int e = it * 256 + t;
            if (AF32) {
                int r = e >> 2, c = (e & 3) << 3;
                const float* p = A32 + (size_t)(m0 + r) * lda + k0 + c;
                float4 f0 = *(const float4*)p;
                float4 f1 = *(const float4*)(p + 4);
                bf162 h0 = __float22bfloat162_rn(make_float2(f0.x, f0.y));
                bf162 h1 = __float22bfloat162_rn(make_float2(f0.z, f0.w));
                bf162 h2 = __float22bfloat162_rn(make_float2(f1.x, f1.y));
                bf162 h3 = __float22bfloat162_rn(make_float2(f1.z, f1.w));
                ra[it].x = *(unsigned*)&h0; ra[it].y = *(unsigned*)&h1;
                ra[it].z = *(unsigned*)&h2; ra[it].w = *(unsigned*)&h3;
            } else if (!AKM) {
                int r = e >> 2, c = (e & 3) << 3;
                ra[it] = *(const uint4*)(A + (size_t)(m0 + r) * lda + k0 + c);
            } else {
                int r = e >> 4, c = (e & 15) << 3;
                ra[it] = *(const uint4*)(A + (size_t)(k0 + r) * lda + m0 + c);
            }
        }
    };
    auto ldB = [&](int k0) {
        #pragma unroll
        for (int it = 0; it < 2; it++) {
            int e = it * 256 + t;
            if (BNK) { int r = e >> 2, c = (e & 3) << 3;
                rb[it] = *(const uint4*)(B + (size_t)(n0 + r) * ldb + k0 + c); }
            else     { int r = e >> 4, c = (e & 15) << 3;
                rb[it] = *(const uint4*)(B + (size_t)(k0 + r) * ldb + n0 + c); }
        }
    };
    auto stAB = [&](int s) {
        bf16* Ap = As + s * ASZ;
        bf16* Bp = Bs + s * BSZ;
        #pragma unroll
        for (int it = 0; it < 2; it++) {
            int e = it * 256 + t;
            if (!AKM) { int r = e >> 2, c = (e & 3) << 3; *(uint4*)&Ap[r * 40 + c] = ra[it]; }
            else      { int r = e >> 4, c = (e & 15) << 3; *(uint4*)&Ap[r * 136 + c] = ra[it]; }
            if (BNK)  { int r = e >> 2, c = (e & 3) << 3; *(uint4*)&Bp[r * 40 + c] = rb[it]; }
            else      { int r = e >> 4, c = (e & 15) << 3; *(uint4*)&Bp[r * 136 + c] = rb[it]; }
        }
    };

    float cc[4][4][4] = {};
    const unsigned asb0 = smem_u32(As), bsb0 = smem_u32(Bs);
    const int nch = K / 32;

    ldA(0); ldB(0); stAB(0);

    for (int ch = 0; ch < nch; ch++) {
        __syncthreads();
        const bool more = (ch + 1 < nch);
        if (more) { ldA((ch + 1) * 32); ldB((ch + 1) * 32); }
        const unsigned asb = asb0 + (unsigned)((ch & 1) * ASZ * 2);
        const unsigned bsb = bsb0 + (unsigned)((ch & 1) * BSZ * 2);

        #pragma unroll
        for (int ks = 0; ks < 2; ks++) {
            const int kk = ks * 16;
            unsigned afr[4][4];
            #pragma unroll
            for (int mi = 0; mi < 4; mi++) {
                unsigned addr;
                if (!AKM) {
                    addr = asb + (unsigned)(((wm0 + mi * 16 + (lane & 15)) * AST
                                  + kk + ((lane >> 4) << 3)) * 2);
                    ldsm_x4(afr[mi], addr);
                } else {
                    addr = asb + (unsigned)(((kk + (lane & 7) + ((lane >> 4) << 3)) * AST
                                  + wm0 + mi * 16 + (((lane >> 3) & 1) << 3)) * 2);
                    ldsm_x4_t(afr[mi], addr);
                }
            }
            unsigned bfr[4][2];
            #pragma unroll
            for (int ni = 0; ni < 4; ni++) {
                unsigned addr;
                if (!BNK) {
                    addr = bsb + (unsigned)(((kk + (lane & 15)) * BST + wn0 + ni * 8) * 2);
                    ldsm_x2_t(bfr[ni], addr);
                } else {
                    addr = bsb + (unsigned)(((wn0 + ni * 8 + (lane & 7)) * BST
                                  + kk + (((lane >> 3) & 1) << 3)) * 2);
                    ldsm_x2(bfr[ni], addr);
                }
            }
            #pragma unroll
            for (int mi = 0; mi < 4; mi++)
                #pragma unroll
                for (int ni = 0; ni < 4; ni++)
                    mma16816(cc[mi][ni], afr[mi], bfr[ni]);
        }

        if (more) stAB((ch + 1) & 1);
    }

    #pragma unroll
    for (int mi = 0; mi < 4; mi++)
        #pragma unroll
        for (int ni = 0; ni < 4; ni++) {
            int r  = m0 + wm0 + mi * 16 + (int)(lane >> 2);
            int ci = n0 + wn0 + ni * 8 + (int)((lane & 3) << 1);
            epi(bz, r,     ci, cc[mi][ni][0], cc[mi][ni][1]);
            epi(bz, r + 8, ci, cc[mi][ni][2], cc[mi][ni][3]);
        }
}

// -------------------- proj GEMM with fused bias + maxpool ------------------
// (round-12 proven; epilogue pooled stores now bf162-granular)
__global__ __launch_bounds__(256, 2) void k_proj(const float* __restrict__ X,
                                                 const bf16* __restrict__ Bw)
{
    constexpr int ASZ = 128 * 40;
    constexpr int BSZ = 32 * 136;
    __shared__ __align__(16) bf16 smbuf[2 * ASZ + 2 * BSZ];   // >= 128*136
    bf16* As = smbuf;
    bf16* Bs = smbuf + 2 * ASZ;

    const int nb = blockIdx.x;             // 0..2
    const int m0 = blockIdx.y * 128;
    const int n0 = nb * 128;

    const int t = threadIdx.x;
    const unsigned lane = t & 31;
    const int w = t >> 5;
    const int wm0 = (w >> 2) * 64;
    const int wn0 = (w & 3) * 32;

    uint4 ra[2], rb[2];
    auto ldA = [&](int k0) {
        #pragma unroll
        for (int it = 0; it < 2; it++) {
            int e = it * 256 + t;
            int r = e >> 2, c = (e & 3) << 3;
            const float* p = X + (size_t)(m0 + r) * CC + k0 + c;
            float4 f0 = *(const float4*)p;
            float4 f1 = *(const float4*)(p + 4);
            bf162 h0 = __float22bfloat162_rn(make_float2(f0.x, f0.y));
            bf162 h1 = __float22bfloat162_rn(make_float2(f0.z, f0.w));
            bf162 h2 = __float22bfloat162_rn(make_float2(f1.x, f1.y));
            bf162 h3 = __float22bfloat162_rn(make_float2(f1.z, f1.w));
            ra[it].x = *(unsigned*)&h0; ra[it].y = *(unsigned*)&h1;
            ra[it].z = *(unsigned*)&h2; ra[it].w = *(unsigned*)&h3;
        }
    };
    auto ldB = [&](int k0) {
        #pragma unroll
        for (int it = 0; it < 2; it++) {
            int e = it * 256 + t;
            int r = e >> 4, c = (e & 15) << 3;
            rb[it] = *(const uint4*)(Bw + (size_t)(k0 + r) * NPROJ + n0 + c);
        }
    };
    auto stAB = [&](int s) {
        bf16* Ap = As + s * ASZ;
        bf16* Bp = Bs + s * BSZ;
        #pragma unroll
        for (int it = 0; it < 2; it++) {
            int e = it * 256 + t;
            { int r = e >> 2, c = (e & 3) << 3; *(uint4*)&Ap[r * 40 + c] = ra[it]; }
            { int r = e >> 4, c = (e & 15) << 3; *(uint4*)&Bp[r * 136 + c] = rb[it]; }
        }
    };

    float cc[4][4][4] = {};
    const unsigned asb0 = smem_u32(As), bsb0 = smem_u32(Bs);

    ldA(0); ldB(0); stAB(0);

    for (int ch = 0; ch < 16; ch++) {                  // K=512
        __syncthreads();
        const bool more = (ch + 1 < 16);
        if (more) { ldA((ch + 1) * 32); ldB((ch + 1) * 32); }
        const unsigned asb = asb0 + (unsigned)((ch & 1) * ASZ * 2);
        const unsigned bsb = bsb0 + (unsigned)((ch & 1) * BSZ * 2);

        #pragma unroll
        for (int ks = 0; ks < 2; ks++) {
            const int kk = ks * 16;
            unsigned afr[4][4];
            #pragma unroll
            for (int mi = 0; mi < 4; mi++)
                ldsm_x4(afr[mi], asb + (unsigned)(((wm0 + mi * 16 + (lane & 15)) * 40
                                     + kk + ((lane >> 4) << 3)) * 2));
            unsigned bfr[4][2];
            #pragma unroll
            for (int ni = 0; ni < 4; ni++)
                ldsm_x2_t(bfr[ni], bsb + (unsigned)(((kk + (lane & 15)) * 136
                                       + wn0 + ni * 8) * 2));
            #pragma unroll
            for (int mi = 0; mi < 4; mi++)
                #pragma unroll
                for (int ni = 0; ni < 4; ni++)
                    mma16816(cc[mi][ni], afr[mi], bfr[ni]);
        }

        if (more) stAB((ch + 1) & 1);
    }

    // ---- stage biased bf16 tile into smem [128][136] ----
    __syncthreads();                       // all compute smem reads done
    #pragma unroll
    for (int mi = 0; mi < 4; mi++)
        #pragma unroll
        for (int ni = 0; ni < 4; ni++) {
            int rl = wm0 + mi * 16 + (int)(lane >> 2);
            int ci = wn0 + ni * 8 + (int)((lane & 3) << 1);
            float b0 = d_bcat[n0 + ci], b1 = d_bcat[n0 + ci + 1];
            bf162 p;
            p.x = __float2bfloat16(cc[mi][ni][0] + b0);
            p.y = __float2bfloat16(cc[mi][ni][1] + b1);
            *(bf162*)&smbuf[rl * 136 + ci] = p;
            bf162 q;
            q.x = __float2bfloat16(cc[mi][ni][2] + b0);
            q.y = __float2bfloat16(cc[mi][ni][3] + b1);
            *(bf162*)&smbuf[(rl + 8) * 136 + ci] = q;
        }
    __syncthreads();

    const int b     = m0 >> 12;                        // batch
    const int ibase = ((m0 & 4095) >> 7) << 5;         // pooled row base
    auto pool2v = [&](int wp, int col) -> bf162 {      // pooled bf162 (2 cols)
        bf162 a0 = *(const bf162*)&smbuf[(2 * wp) * 136 + col];
        bf162 a1 = *(const bf162*)&smbuf[(2 * wp + 1) * 136 + col];
        bf162 a2 = *(const bf162*)&smbuf[(64 + 2 * wp) * 136 + col];
        bf162 a3 = *(const bf162*)&smbuf[(65 + 2 * wp) * 136 + col];
        bf162 o;
        o.x = __float2bfloat16(fmaxf(fmaxf(__bfloat162float(a0.x), __bfloat162float(a1.x)),
                                     fmaxf(__bfloat162float(a2.x), __bfloat162float(a3.x))));
        o.y = __float2bfloat16(fmaxf(fmaxf(__bfloat162float(a0.y), __bfloat162float(a1.y)),
                                     fmaxf(__bfloat162float(a2.y), __bfloat162float(a3.y))));
        return o;
    };

    if (nb == 0) {
        // theta: cols 0..63 -> compact d_thetabf
        {
            const int r = t >> 1, half = t & 1;
            const unsigned* sp = (const unsigned*)&smbuf[r * 136 + half * 32];
            unsigned* gp = (unsigned*)&d_thetabf[(size_t)(m0 + r) * CFG + half * 32];
            #pragma unroll
            for (int k = 0; k < 16; k++) gp[k] = sp[k];
        }
        // phi: cols 64..127 -> 2x2 pooled (1024 bf162 outputs)
        #pragma unroll
        for (int k = 0; k < 4; k++) {
            int o = k * 256 + t;
            int wp = o >> 5, c2 = (o & 31) << 1;
            *(bf162*)&d_phibf[((size_t)b * HWD + ibase + wp) * CFG + c2]
                = pool2v(wp, 64 + c2);
        }
    } else {
        // g: 128 cols -> 2x2 pooled (2048 bf162 outputs)
        #pragma unroll
        for (int k = 0; k < 8; k++) {
            int o = k * 256 + t;
            int wp = o >> 6, c2 = (o & 63) << 1;
            *(bf162*)&d_gbf[((size_t)b * HWD + ibase + wp) * CHDIM + (nb - 1) * 128 + c2]
                = pool2v(wp, c2);
        }
    }
}

// -------------------- dedicated e-GEMM: phi reuse over 8 j-tiles -----------
// (round-12 proven, verbatim)
__global__ __launch_bounds__(256, 2) void k_egemm()
{
    constexpr int CSZ = 128 * 40;
    __shared__ __align__(16) bf16 As[2 * CSZ];
    __shared__ __align__(16) bf16 Bs[2][2 * CSZ];
    __shared__ float rs[128][4];

    const int jg = blockIdx.x;
    const int i0 = blockIdx.y * 128;
    const int bz = blockIdx.z;
    const bf16* Aph = d_phibf   + (size_t)bz * HWD * CFG;
    const bf16* Bth = d_thetabf + (size_t)bz * HW * CFG;
    bf16* eb = d_ebf + ((size_t)bz * HWD + i0) * HW;

    const int t = threadIdx.x;
    const unsigned lane = t & 31;
    const int w = t >> 5;
    const int wm0 = (w >> 2) * 64;
    const int wn0 = (w & 3) * 32;
    const unsigned asb = smem_u32(As);

    #pragma unroll
    for (int ch = 0; ch < 2; ch++)
        #pragma unroll
        for (int it = 0; it < 2; it++) {
            int e = it * 256 + t;
            int r = e >> 2, c = (e & 3) << 3;
            *(uint4*)&As[ch * CSZ + r * 40 + c] =
                *(const uint4*)(Aph + (size_t)(i0 + r) * CFG + ch * 32 + c);
        }

    uint4 rB[4];
    auto ldB = [&](int jt) {
        const int j0 = jg * 1024 + jt * 128;
        #pragma unroll
        for (int ch = 0; ch < 2; ch++)
            #pragma unroll
            for (int it = 0; it < 2; it++) {
                int e = it * 256 + t;
                int r = e >> 2, c = (e & 3) << 3;
                rB[ch * 2 + it] =
                    *(const uint4*)(Bth + (size_t)(j0 + r) * CFG + ch * 32 + c);
            }
    };
    auto stB = [&](int s) {
        #pragma unroll
        for (int ch = 0; ch < 2; ch++)
            #pragma unroll
            for (int it = 0; it < 2; it++) {
                int e = it * 256 + t;
                int r = e >> 2, c = (e & 3) << 3;
                *(uint4*)&Bs[s][ch * CSZ + r * 40 + c] = rB[ch * 2 + it];
            }
    };

    float zp[4][2];
    #pragma unroll
    for (int mi = 0; mi < 4; mi++) { zp[mi][0] = 0.f; zp[mi][1] = 0.f; }

    ldB(0); stB(0);

    for (int jt = 0; jt < 8; jt++) {
        __syncthreads();
        const bool more = (jt + 1 < 8);
        if (more) ldB(jt + 1);

        const unsigned bsb = smem_u32(Bs[jt & 1]);
        float cc[4][4][4] = {};
        #pragma unroll
        for (int ch = 0; ch < 2; ch++) {
            const unsigned asc = asb + (unsigned)(ch * CSZ * 2);
            const unsigned bsc = bsb + (unsigned)(ch * CSZ * 2);
            #pragma unroll
            for (int ks = 0; ks < 2; ks++) {
                const int kk = ks * 16;
                unsigned afr[4][4];
                #pragma unroll
                for (int mi = 0; mi < 4; mi++)
                    ldsm_x4(afr[mi], asc + (unsigned)(((wm0 + mi * 16 + (lane & 15)) * 40
                                         + kk + ((lane >> 4) << 3)) * 2));
                unsigned bfr[4][2];
                #pragma unroll
                for (int ni = 0; ni < 4; ni++)
                    ldsm_x2(bfr[ni], bsc + (unsigned)(((wn0 + ni * 8 + (lane & 7)) * 40
                                         + kk + (((lane >> 3) & 1) << 3)) * 2));
                #pragma unroll
                for (int mi = 0; mi < 4; mi++)
                    #pragma unroll
                    for (int ni = 0; ni < 4; ni++)
                        mma16816(cc[mi][ni], afr[mi], bfr[ni]);
            }
        }

        const int jbase = jg * 1024 + jt * 128;
        #pragma unroll
        for (int mi = 0; mi < 4; mi++) {
            const int rl = wm0 + mi * 16 + (int)(lane >> 2);
            #pragma unroll
            for (int ni = 0; ni < 4; ni++) {
                const int cj = jbase + wn0 + ni * 8 + (int)((lane & 3) << 1);
                float e0 = __expf(cc[mi][ni][0]), e1 = __expf(cc[mi][ni][1]);
                float e2 = __expf(cc[mi][ni][2]), e3 = __expf(cc[mi][ni][3]);
                bf162 p; p.x = __float2bfloat16(e0); p.y = __float2bfloat16(e1);
                *(bf162*)&eb[(size_t)rl * HW + cj] = p;
                bf162 q; q.x = __float2bfloat16(e2); q.y = __float2bfloat16(e3);
                *(bf162*)&eb[(size_t)(rl + 8) * HW + cj] = q;
                zp[mi][0] += e0 + e1;
                zp[mi][1] += e2 + e3;
            }
        }

        if (more) stB((jt + 1) & 1);
    }

    #pragma unroll
    for (int mi = 0; mi < 4; mi++) {
        float rp0 = zp[mi][0], rp1 = zp[mi][1];
        rp0 += __shfl_xor_sync(0xffffffffu, rp0, 1);
        rp0 += __shfl_xor_sync(0xffffffffu, rp0, 2);
        rp1 += __shfl_xor_sync(0xffffffffu, rp1, 1);
        rp1 += __shfl_xor_sync(0xffffffffu, rp1, 2);
        if ((lane & 3) == 0) {
            int rl = wm0 + mi * 16 + (int)(lane >> 2);
            rs[rl][w & 3]     = rp0;
            rs[rl + 8][w & 3] = rp1;
        }
    }
    __syncthreads();
    if (t < 128) {
        float z = (rs[t][0] + rs[t][1]) + (rs[t][2] + rs[t][3]);
        d_part[((size_t)bz * HWD + i0 + t) * 4 + jg] = z;
    }
}

// -------------------- prep: weights/biases to bf16 --------------------------
__global__ __launch_bounds__(256) void k_cvt_w(
    const float* __restrict__ tw, const float* __restrict__ pw, const float* __restrict__ gw,
    const float* __restrict__ tb, const float* __restrict__ pb, const float* __restrict__ gb,
    const float* __restrict__ ow)
{
    int i = blockIdx.x * 256 + threadIdx.x;
    const int W1 = CC * NPROJ, W2 = W1 + CHDIM * CC;
    if (i < W1) {
        int r = i / NPROJ, c = i % NPROJ;
        float v = (c < 64) ? tw[r * 64 + c] : (c < 128) ? pw[r * 64 + c - 64]
                                            : gw[r * 256 + c - 128];
        d_wcat[i] = __float2bfloat16(v);
    } else if (i < W2) {
        int j = i - W1;
        d_owbf[j] = __float2bfloat16(ow[j]);
    } else if (i < W2 + NPROJ) {
        int c = i - W2;
        d_bcat[c] = (c < 64) ? tb[c] : (c < 128) ? pb[c - 64] : gb[c - 128];
    }
}

// -------------------- fused Z reduce + g scaling (vectorized 8x) ------------
__global__ __launch_bounds__(256) void k_zgscale() {
    int idx = blockIdx.x * 256 + threadIdx.x;     // uint4 groups: 8*1024*32
    if (idx >= BB * HWD * 32) return;
    int row = idx >> 5;                           // (b*1024 + i)
    const float* p = &d_part[(size_t)row * 4];
    float iz = 1.0f / ((p[0] + p[1]) + (p[2] + p[3]));
    uint4 v = *(uint4*)&d_gbf[(size_t)idx * 8];
    bf162* h = (bf162*)&v;
    #pragma unroll
    for (int k = 0; k < 4; k++) {
        h[k].x = __float2bfloat16(__bfloat162float(h[k].x) * iz);
        h[k].y = __float2bfloat16(__bfloat162float(h[k].y) * iz);
    }
    *(uint4*)&d_gbf[(size_t)idx * 8] = v;
}

// -------------------- launch -----------------------------------------------
extern "C" void kernel_launch(void* const* d_in, const int* in_sizes, int n_in,
                              void* d_out, int out_size)
{
    const float* x  = (const float*)d_in[0];
    const float* tw = (const float*)d_in[1];
    const float* tb = (const float*)d_in[2];
    const float* pw = (const float*)d_in[3];
    const float* pb = (const float*)d_in[4];
    const float* gw = (const float*)d_in[5];
    const float* gb = (const float*)d_in[6];
    const float* ow = (const float*)d_in[7];
    const float* ob = (const float*)d_in[8];
    const float* gm = (const float*)d_in[9];
    float* out = (float*)d_out;

    void *p_wcat, *p_owbf, *p_gbf, *p_ebf, *p_obf;
    cudaGetSymbolAddress(&p_wcat, d_wcat);
    cudaGetSymbolAddress(&p_owbf, d_owbf);
    cudaGetSymbolAddress(&p_gbf,  d_gbf);
    cudaGetSymbolAddress(&p_ebf,  d_ebf);
    cudaGetSymbolAddress(&p_obf,  d_obf);

    // 0) weights to bf16 (x converted on the fly inside proj GEMM)
    k_cvt_w<<<(CC * NPROJ + CHDIM * CC + NPROJ + 255) / 256, 256>>>(tw, pw, gw, tb, pb, gb, ow);

    // 1) projections + bias + fused 2x2 maxpool -> theta (compact), phi, g
    k_proj<<<dim3(3, MROWS / 128), 256>>>(x, (const bf16*)p_wcat);

    // 2) e = exp(phi @ theta^T): phi reuse over 8 j-tiles per block
    k_egemm<<<dim3(HW / 1024, HWD / 128, BB), 256>>>();

    // 3) fused Z reduction + 1/Z fold into g rows (vectorized)
    k_zgscale<<<(BB * HWD * 32 + 255) / 256, 256>>>();

    // 4) o = e^T @ g' per batch: [4096,1024] @ [1024,256], A is [k][m]
    gemm_bf16<true, false, false, EpiO><<<dim3(CHDIM / 128, HW / 128, BB), 256>>>(
        p_ebf, (const bf16*)p_gbf, HW, CHDIM, HWD,
        (size_t)HWD * HW, (size_t)HWD * CHDIM, EpiO{});

    // 5) out = gamma*(o @ o3_w + b) + x: [32768,256] @ [256,512]
    EpiFinal ef{x, ob, gm, out};
    gemm_bf16<false, false, false, EpiFinal><<<dim3(CC / 128, MROWS / 128, 1), 256>>>(
        p_obf, (const bf16*)p_owbf, CHDIM, CC, CHDIM, 0, 0, ef);
}